// round 1
// baseline (speedup 1.0000x reference)
#include <cuda_runtime.h>

#define NEG_SLOPE 0.2f

// x: [B=8, C=256, H=128, W=128] f32
// row = b*C + c, 2048 rows, each 16384 floats (64 KB)
static constexpr int NROWS = 2048;     // B*C
static constexpr int ROW_ELEMS = 16384; // H*W
static constexpr int ROW_VEC4 = ROW_ELEMS / 4; // 4096
static constexpr int B = 8;
static constexpr int C = 256;
static constexpr int CS = 16;

__device__ float g_y[NROWS];     // pooled means [B*C]
__device__ float g_gate[NROWS];  // sigmoid gates [B*C]

// ---------------------------------------------------------------------------
// Kernel 1: global average pool. One CTA per row.
// ---------------------------------------------------------------------------
__global__ __launch_bounds__(256) void gap_kernel(const float* __restrict__ x) {
    const int row = blockIdx.x;
    const float4* __restrict__ xr = reinterpret_cast<const float4*>(x) + (size_t)row * ROW_VEC4;
    const int tid = threadIdx.x;

    float s = 0.f;
    // 4096 float4 / 256 threads = 16 iterations, fully coalesced
#pragma unroll
    for (int i = 0; i < ROW_VEC4 / 256; i++) {
        float4 v = xr[tid + i * 256];
        s += (v.x + v.y) + (v.z + v.w);
    }

    // warp reduce
#pragma unroll
    for (int off = 16; off > 0; off >>= 1)
        s += __shfl_xor_sync(0xFFFFFFFF, s, off);

    __shared__ float warp_sums[8];
    if ((tid & 31) == 0) warp_sums[tid >> 5] = s;
    __syncthreads();
    if (tid == 0) {
        float tot = 0.f;
#pragma unroll
        for (int w = 0; w < 8; w++) tot += warp_sums[w];
        g_y[row] = tot * (1.0f / ROW_ELEMS);
    }
}

// ---------------------------------------------------------------------------
// Kernel 2: tiny FC stack. Single CTA, 256 threads.
//   y1[b][s] = leaky(sum_c w1[s][c]*y[b][c] + b1[s])       (8*16 = 128 dots)
//   gate[b][c] = sigmoid(sum_s w2[c][s]*y1[b][s] + b2[c])  (8*256 outputs)
// ---------------------------------------------------------------------------
__global__ __launch_bounds__(256) void fc_kernel(const float* __restrict__ w1,
                                                 const float* __restrict__ b1,
                                                 const float* __restrict__ w2,
                                                 const float* __restrict__ b2) {
    __shared__ float sh_y[NROWS > 2048 ? NROWS : 2048]; // 8 KB: pooled y
    __shared__ float sh_y1[B * CS];                     // 128 floats

    const int tid = threadIdx.x;

    // load pooled y into shared
#pragma unroll
    for (int i = 0; i < NROWS / 256; i++)
        sh_y[tid + i * 256] = g_y[tid + i * 256];
    __syncthreads();

    // squeeze GEMV + LeakyReLU: 128 outputs, one per thread for tid < 128
    if (tid < B * CS) {
        const int b = tid / CS;
        const int s = tid % CS;
        const float* wrow = w1 + s * C;
        const float* yrow = sh_y + b * C;
        float acc = 0.f;
#pragma unroll 8
        for (int c = 0; c < C; c++) acc += wrow[c] * yrow[c];
        acc += b1[s];
        sh_y1[tid] = (acc >= 0.f) ? acc : NEG_SLOPE * acc;
    }
    __syncthreads();

    // excite GEMV + sigmoid: 2048 outputs, 8 per thread
#pragma unroll
    for (int i = 0; i < NROWS / 256; i++) {
        const int idx = tid + i * 256;   // idx = b*C + c
        const int b = idx / C;
        const int c = idx % C;
        const float* wrow = w2 + c * CS;
        const float* y1row = sh_y1 + b * CS;
        float acc = b2[c];
#pragma unroll
        for (int s = 0; s < CS; s++) acc += wrow[s] * y1row[s];
        g_gate[idx] = 1.0f / (1.0f + __expf(-acc));
    }
}

// ---------------------------------------------------------------------------
// Kernel 3: channel-wise scale. One CTA per row, streams 64 KB.
// ---------------------------------------------------------------------------
__global__ __launch_bounds__(256) void scale_kernel(const float* __restrict__ x,
                                                    float* __restrict__ out) {
    const int row = blockIdx.x;
    const float g = g_gate[row];
    const float4* __restrict__ xr = reinterpret_cast<const float4*>(x) + (size_t)row * ROW_VEC4;
    float4* __restrict__ orow = reinterpret_cast<float4*>(out) + (size_t)row * ROW_VEC4;
    const int tid = threadIdx.x;

#pragma unroll
    for (int i = 0; i < ROW_VEC4 / 256; i++) {
        float4 v = xr[tid + i * 256];
        v.x *= g; v.y *= g; v.z *= g; v.w *= g;
        orow[tid + i * 256] = v;
    }
}

extern "C" void kernel_launch(void* const* d_in, const int* in_sizes, int n_in,
                              void* d_out, int out_size) {
    const float* x  = (const float*)d_in[0];
    const float* w1 = (const float*)d_in[1];
    const float* b1 = (const float*)d_in[2];
    const float* w2 = (const float*)d_in[3];
    const float* b2 = (const float*)d_in[4];
    float* out = (float*)d_out;

    gap_kernel<<<NROWS, 256>>>(x);
    fc_kernel<<<1, 256>>>(w1, b1, w2, b2);
    scale_kernel<<<NROWS, 256>>>(x, out);
}

// round 2
// speedup vs baseline: 1.0725x; 1.0725x over previous
#include <cuda_runtime.h>

#define NEG_SLOPE 0.2f

// x: [B=8, C=256, H=128, W=128] f32
// row = b*C + c, 2048 rows of 16384 floats (64 KB each)
static constexpr int NROWS = 2048;      // B*C
static constexpr int ROW_ELEMS = 16384; // H*W
static constexpr int ROW_VEC4 = ROW_ELEMS / 4; // 4096
static constexpr int B = 8;
static constexpr int C = 256;
static constexpr int CS = 16;

__device__ float g_y[NROWS];            // pooled means [B*C]
__device__ float g_gate[NROWS];         // sigmoid gates [B*C]
__device__ unsigned int g_counter;      // zero-init; self-resetting

// ---------------------------------------------------------------------------
// Kernel 1: global average pool, one CTA per row. The LAST CTA to finish also
// runs the tiny FC stack (squeeze -> LeakyReLU -> excite -> sigmoid), removing
// a separate kernel launch + dependency stall.
// ---------------------------------------------------------------------------
__global__ __launch_bounds__(256) void gap_fc_kernel(const float* __restrict__ x,
                                                     const float* __restrict__ w1,
                                                     const float* __restrict__ b1,
                                                     const float* __restrict__ w2,
                                                     const float* __restrict__ b2) {
    const int row = blockIdx.x;
    const float4* __restrict__ xr = reinterpret_cast<const float4*>(x) + (size_t)row * ROW_VEC4;
    const int tid = threadIdx.x;

    float s = 0.f;
#pragma unroll
    for (int i = 0; i < ROW_VEC4 / 256; i++) {
        float4 v = xr[tid + i * 256];
        s += (v.x + v.y) + (v.z + v.w);
    }

#pragma unroll
    for (int off = 16; off > 0; off >>= 1)
        s += __shfl_xor_sync(0xFFFFFFFF, s, off);

    __shared__ float warp_sums[8];
    __shared__ bool is_last;
    if ((tid & 31) == 0) warp_sums[tid >> 5] = s;
    __syncthreads();
    if (tid == 0) {
        float tot = 0.f;
#pragma unroll
        for (int w = 0; w < 8; w++) tot += warp_sums[w];
        g_y[row] = tot * (1.0f / ROW_ELEMS);
        __threadfence();  // publish g_y before signaling
        unsigned int prev = atomicAdd(&g_counter, 1u);
        is_last = (prev == NROWS - 1);
    }
    __syncthreads();

    if (!is_last) return;

    // ---- FC tail (one CTA, 256 threads) ----
    __shared__ float sh_y[NROWS];   // 8 KB pooled means
    __shared__ float sh_y1[B * CS]; // 128 floats

#pragma unroll
    for (int i = 0; i < NROWS / 256; i++)
        sh_y[tid + i * 256] = g_y[tid + i * 256];
    __syncthreads();

    // squeeze GEMV + LeakyReLU: 128 outputs (b,s), one per thread
    if (tid < B * CS) {
        const int b = tid / CS;
        const int ss = tid % CS;
        const float* wrow = w1 + ss * C;
        const float* yrow = sh_y + b * C;
        float acc = 0.f;
#pragma unroll 8
        for (int c = 0; c < C; c++) acc += wrow[c] * yrow[c];
        acc += b1[ss];
        sh_y1[tid] = (acc >= 0.f) ? acc : NEG_SLOPE * acc;
    }
    __syncthreads();

    // excite GEMV + sigmoid: 2048 gates, 8 per thread
#pragma unroll
    for (int i = 0; i < NROWS / 256; i++) {
        const int idx = tid + i * 256;  // idx = b*C + c
        const int b = idx / C;
        const int c = idx % C;
        const float* wrow = w2 + c * CS;
        const float* y1row = sh_y1 + b * CS;
        float acc = b2[c];
#pragma unroll
        for (int ss = 0; ss < CS; ss++) acc += wrow[ss] * y1row[ss];
        g_gate[idx] = 1.0f / (1.0f + __expf(-acc));
    }

    // reset counter for next graph replay (deterministic across calls)
    if (tid == 0) g_counter = 0u;
}

// ---------------------------------------------------------------------------
// Kernel 2: channel-wise scale. REVERSE row order so the first-scheduled CTAs
// re-read the tail of x that gap_fc just left resident in L2 (134MB data vs
// 126MB L2 -> most of the re-read should be L2 hits instead of DRAM).
// ---------------------------------------------------------------------------
__global__ __launch_bounds__(256) void scale_kernel(const float* __restrict__ x,
                                                    float* __restrict__ out) {
    const int row = (NROWS - 1) - blockIdx.x;
    const float g = g_gate[row];
    const float4* __restrict__ xr = reinterpret_cast<const float4*>(x) + (size_t)row * ROW_VEC4;
    float4* __restrict__ orow = reinterpret_cast<float4*>(out) + (size_t)row * ROW_VEC4;
    const int tid = threadIdx.x;

#pragma unroll
    for (int i = 0; i < ROW_VEC4 / 256; i++) {
        float4 v = xr[tid + i * 256];
        v.x *= g; v.y *= g; v.z *= g; v.w *= g;
        orow[tid + i * 256] = v;
    }
}

extern "C" void kernel_launch(void* const* d_in, const int* in_sizes, int n_in,
                              void* d_out, int out_size) {
    const float* x  = (const float*)d_in[0];
    const float* w1 = (const float*)d_in[1];
    const float* b1 = (const float*)d_in[2];
    const float* w2 = (const float*)d_in[3];
    const float* b2 = (const float*)d_in[4];
    float* out = (float*)d_out;

    gap_fc_kernel<<<NROWS, 256>>>(x, w1, b1, w2, b2);
    scale_kernel<<<NROWS, 256>>>(x, out);
}